// round 1
// baseline (speedup 1.0000x reference)
#include <cuda_runtime.h>
#include <math.h>

// Problem dims
#define NB   128     // tokens
#define DD   2560    // D
#define DN   5120    // DIN
#define SS   16
#define RR   160
#define PJ   192     // R + 2S

// ---------------- scratch (device globals: allocation-free) ----------------
__device__ float g_xs  [NB * DN];   // x @ ssm_proj (split-K accumulated)
__device__ float g_res [NB * DN];   // x @ mlp_proj
__device__ float g_u   [NB * DN];   // silu(conv_out)
__device__ float g_proj[NB * PJ];   // u @ x_proj_w
__device__ float g_g   [NB * DN];   // y * res

// ---------------- f32x2 helpers ----------------
__device__ __forceinline__ void fma2(unsigned long long& acc,
                                     unsigned long long a,
                                     unsigned long long b) {
    asm volatile("fma.rn.f32x2 %0, %1, %2, %0;" : "+l"(acc) : "l"(a), "l"(b));
}
__device__ __forceinline__ unsigned long long pack2(float lo, float hi) {
    unsigned long long r;
    asm("mov.b64 %0, {%1, %2};" : "=l"(r)
        : "r"(__float_as_uint(lo)), "r"(__float_as_uint(hi)));
    return r;
}
__device__ __forceinline__ void unpack2(unsigned long long v, float& lo, float& hi) {
    unsigned int a, b;
    asm("mov.b64 {%0, %1}, %2;" : "=r"(a), "=r"(b) : "l"(v));
    lo = __uint_as_float(a);
    hi = __uint_as_float(b);
}

// ---------------- zero scratch + output ----------------
__global__ void zero_all(float* __restrict__ out) {
    int i = blockIdx.x * blockDim.x + threadIdx.x;  // grid covers NB*DN
    if (i < NB * DN) { g_xs[i] = 0.0f; g_res[i] = 0.0f; }
    if (i < NB * PJ) g_proj[i] = 0.0f;
    if (i < NB * DD) out[i] = 0.0f;
}

// ---------------- generic split-K SGEMM, C += A@B via atomics ----------------
// A: [128, K] row-major (lda), B: [K, N] row-major (ldb = N), C: [128, N].
// grid = (N/64, KSPLIT), block = 256. BM=128, BN=64, BK=16.
// Thread (ty,tx) of 16x16 computes rows ty*8..+7 (as 4 row-pairs), cols tx*4..+3.
__global__ __launch_bounds__(256, 3)
void sgemm_atomic(const float* __restrict__ A, const float* __restrict__ B,
                  float* __restrict__ C, int K, int N, int lda, int kslice) {
    __shared__ float As[16][128];
    __shared__ float Bs[16][64];

    const int n0 = blockIdx.x * 64;
    int k0 = blockIdx.y * kslice;
    int kend = k0 + kslice;
    if (kend > K) kend = K;

    const int t  = threadIdx.x;
    const int ty = t >> 4;
    const int tx = t & 15;

    // A-tile loader mapping: row an, k-segment aseg (8 floats each)
    const int an   = t >> 1;
    const int aseg = t & 1;
    // B-tile loader mapping: row bk, 4 cols at bj
    const int bk = t >> 4;
    const int bj = (t & 15) << 2;

    unsigned long long acc[4][4];
#pragma unroll
    for (int i = 0; i < 4; i++)
#pragma unroll
        for (int j = 0; j < 4; j++) acc[i][j] = 0ull;

    for (; k0 < kend; k0 += 16) {
        const float4 av0 = *reinterpret_cast<const float4*>(A + an * lda + k0 + aseg * 8);
        const float4 av1 = *reinterpret_cast<const float4*>(A + an * lda + k0 + aseg * 8 + 4);
        const float4 bv  = *reinterpret_cast<const float4*>(B + (k0 + bk) * N + n0 + bj);

        As[aseg * 8 + 0][an] = av0.x;
        As[aseg * 8 + 1][an] = av0.y;
        As[aseg * 8 + 2][an] = av0.z;
        As[aseg * 8 + 3][an] = av0.w;
        As[aseg * 8 + 4][an] = av1.x;
        As[aseg * 8 + 5][an] = av1.y;
        As[aseg * 8 + 6][an] = av1.z;
        As[aseg * 8 + 7][an] = av1.w;
        *reinterpret_cast<float4*>(&Bs[bk][bj]) = bv;
        __syncthreads();

#pragma unroll
        for (int kk = 0; kk < 16; kk++) {
            unsigned long long a[4];
#pragma unroll
            for (int i = 0; i < 4; i++)
                a[i] = *reinterpret_cast<const unsigned long long*>(&As[kk][ty * 8 + 2 * i]);
            const float4 b4 = *reinterpret_cast<const float4*>(&Bs[kk][tx * 4]);
            unsigned long long b[4];
            b[0] = pack2(b4.x, b4.x);
            b[1] = pack2(b4.y, b4.y);
            b[2] = pack2(b4.z, b4.z);
            b[3] = pack2(b4.w, b4.w);
#pragma unroll
            for (int i = 0; i < 4; i++)
#pragma unroll
                for (int j = 0; j < 4; j++) fma2(acc[i][j], a[i], b[j]);
        }
        __syncthreads();
    }

#pragma unroll
    for (int i = 0; i < 4; i++) {
        const int r0 = ty * 8 + 2 * i;
#pragma unroll
        for (int j = 0; j < 4; j++) {
            float lo, hi;
            unpack2(acc[i][j], lo, hi);
            const int c = n0 + tx * 4 + j;
            atomicAdd(&C[r0 * N + c], lo);
            atomicAdd(&C[(r0 + 1) * N + c], hi);
        }
    }
}

// ---------------- conv (depthwise 4-tap on last state) + SiLU ----------------
// states = (conv_state1, conv_state2, conv_state3, xs); conv_state0 is unused.
__global__ void conv_silu(const float* __restrict__ cs1, const float* __restrict__ cs2,
                          const float* __restrict__ cs3, const float* __restrict__ cw,
                          const float* __restrict__ cb) {
    int i = blockIdx.x * blockDim.x + threadIdx.x;
    if (i >= NB * DN) return;
    int d = i % DN;
    float v = cb[d]
            + cw[0 * DN + d] * cs1[i]
            + cw[1 * DN + d] * cs2[i]
            + cw[2 * DN + d] * cs3[i]
            + cw[3 * DN + d] * g_xs[i];
    g_u[i] = v / (1.0f + expf(-v));   // silu
}

// ---------------- fused dt-GEMM + softplus + SSM scan + gate ----------------
// grid = (DN/256, NB/8), block = 256. Each thread owns one d, 8 tokens.
__global__ __launch_bounds__(256)
void ssm_kernel(const float* __restrict__ dt_w,    // [160, 5120]
                const float* __restrict__ dt_b,    // [5120]
                const float* __restrict__ A_log,   // [5120, 16]
                const float* __restrict__ state,   // [128, 5120, 16]
                const float* __restrict__ D_param) // [5120]
{
    const int d  = blockIdx.x * 256 + threadIdx.x;
    const int nb = blockIdx.y * 8;

    __shared__ float pj[8][PJ];
    for (int i = threadIdx.x; i < 8 * PJ; i += 256)
        pj[i / PJ][i % PJ] = g_proj[(nb + i / PJ) * PJ + (i % PJ)];
    __syncthreads();

    // dt_pre[i] = bias + proj[n, :160] @ dt_proj_w[:, d]
    float dtp[8];
    const float bias = dt_b[d];
#pragma unroll
    for (int i = 0; i < 8; i++) dtp[i] = bias;
#pragma unroll 4
    for (int r = 0; r < RR; r++) {
        const float w = dt_w[r * DN + d];
#pragma unroll
        for (int i = 0; i < 8; i++) dtp[i] += pj[i][r] * w;
    }

    float Aa[SS];
#pragma unroll
    for (int s = 0; s < SS; s++) Aa[s] = -expf(A_log[d * SS + s]);
    const float Dv = D_param[d];

#pragma unroll
    for (int i = 0; i < 8; i++) {
        const int n = nb + i;
        const float x  = dtp[i];
        const float dt = (x > 20.0f) ? x : log1pf(expf(x));  // softplus
        const float uv = g_u[n * DN + d];
        const float rv = g_res[n * DN + d];
        const float4* st = reinterpret_cast<const float4*>(state + ((long)n * DN + d) * SS);
        float y = 0.0f;
#pragma unroll
        for (int q = 0; q < 4; q++) {
            const float4 sv = st[q];
            {   const int s = q * 4 + 0;
                const float h = expf(dt * Aa[s]) * sv.x + dt * pj[i][RR + s] * uv;
                y += h * pj[i][RR + SS + s]; }
            {   const int s = q * 4 + 1;
                const float h = expf(dt * Aa[s]) * sv.y + dt * pj[i][RR + s] * uv;
                y += h * pj[i][RR + SS + s]; }
            {   const int s = q * 4 + 2;
                const float h = expf(dt * Aa[s]) * sv.z + dt * pj[i][RR + s] * uv;
                y += h * pj[i][RR + SS + s]; }
            {   const int s = q * 4 + 3;
                const float h = expf(dt * Aa[s]) * sv.w + dt * pj[i][RR + s] * uv;
                y += h * pj[i][RR + SS + s]; }
        }
        y += Dv * uv;
        g_g[n * DN + d] = y * rv;
    }
}

// ---------------- launcher ----------------
extern "C" void kernel_launch(void* const* d_in, const int* in_sizes, int n_in,
                              void* d_out, int out_size) {
    const float* x        = (const float*)d_in[0];
    // d_in[1] = conv_state0 (unused by the reference)
    const float* cs1      = (const float*)d_in[2];
    const float* cs2      = (const float*)d_in[3];
    const float* cs3      = (const float*)d_in[4];
    const float* state    = (const float*)d_in[5];
    const float* ssm_proj = (const float*)d_in[6];
    const float* mlp_proj = (const float*)d_in[7];
    const float* down_prj = (const float*)d_in[8];
    const float* conv_w   = (const float*)d_in[9];
    const float* conv_b   = (const float*)d_in[10];
    const float* x_proj_w = (const float*)d_in[11];
    const float* dt_w     = (const float*)d_in[12];
    const float* dt_b     = (const float*)d_in[13];
    const float* A_log    = (const float*)d_in[14];
    const float* Dp       = (const float*)d_in[15];
    float* out = (float*)d_out;

    void *p_xs, *p_res, *p_u, *p_proj, *p_g;
    cudaGetSymbolAddress(&p_xs,   g_xs);
    cudaGetSymbolAddress(&p_res,  g_res);
    cudaGetSymbolAddress(&p_u,    g_u);
    cudaGetSymbolAddress(&p_proj, g_proj);
    cudaGetSymbolAddress(&p_g,    g_g);

    // 0) zero accumulators + output
    zero_all<<<(NB * DN + 255) / 256, 256>>>(out);

    // 1) xs = x @ ssm_proj   (K=2560, N=5120, split-K 4)
    sgemm_atomic<<<dim3(DN / 64, 4), 256>>>(x, ssm_proj, (float*)p_xs,
                                            DD, DN, DD, DD / 4);
    // 2) res = x @ mlp_proj
    sgemm_atomic<<<dim3(DN / 64, 4), 256>>>(x, mlp_proj, (float*)p_res,
                                            DD, DN, DD, DD / 4);
    // 3) u = silu(conv_bias + w0*cs1 + w1*cs2 + w2*cs3 + w3*xs)
    conv_silu<<<(NB * DN + 255) / 256, 256>>>(cs1, cs2, cs3, conv_w, conv_b);

    // 4) proj = u @ x_proj_w  (K=5120, N=192, split-K 40)
    sgemm_atomic<<<dim3(PJ / 64, 40), 256>>>((const float*)p_u, x_proj_w,
                                             (float*)p_proj, DN, PJ, DN, 128);

    // 5) dt GEMM + softplus + SSM scan + D*u + gate by res -> g_g
    ssm_kernel<<<dim3(DN / 256, NB / 8), 256>>>(dt_w, dt_b, A_log, state, Dp);

    // 6) out = g_g @ down_proj  (K=5120, N=2560, split-K 8)
    sgemm_atomic<<<dim3(DD / 64, 8), 256>>>((const float*)p_g, down_prj, out,
                                            DN, DD, DN, DN / 8);
}